// round 17
// baseline (speedup 1.0000x reference)
#include <cuda_runtime.h>
#include <cuda_bf16.h>
#include <cuda_fp16.h>
#include <math_constants.h>
#include <cstdint>

#define B_   2
#define S_   2048
#define H_   768
#define NH_  12
#define HD_  64
#define ROWS (B_*S_)          // 4096

// ---------------- scratch ----------------
__device__ __align__(256) __half g_xn16[ROWS*H_];
__device__ __align__(256) __half g_cr16[ROWS*H_];
__device__ __align__(256) __half g_q16 [ROWS*H_];   // pre-scaled by 0.125*log2e
__device__ __align__(256) __half g_k16 [ROWS*H_];
__device__ __align__(256) __half g_v16 [ROWS*H_];
__device__ __align__(256) __half g_ao16[ROWS*H_];
__device__ __align__(256) __half g_wt_hi[4*H_*H_];
__device__ __align__(256) __half g_wt_lo[4*H_*H_];
__device__ __align__(256) __half g_maskb[(size_t)B_*S_*S_];   // additive bias: 0 or -30000

// ---------------- helpers ----------------
__device__ __forceinline__ unsigned sa(const void* p) {
    return (unsigned)__cvta_generic_to_shared(p);
}
__device__ __forceinline__ void ldsm4(unsigned r[4], unsigned addr) {
    asm volatile("ldmatrix.sync.aligned.m8n8.x4.shared.b16 {%0,%1,%2,%3}, [%4];"
        : "=r"(r[0]), "=r"(r[1]), "=r"(r[2]), "=r"(r[3]) : "r"(addr));
}
__device__ __forceinline__ void ldsm4t(unsigned r[4], unsigned addr) {
    asm volatile("ldmatrix.sync.aligned.m8n8.x4.trans.shared.b16 {%0,%1,%2,%3}, [%4];"
        : "=r"(r[0]), "=r"(r[1]), "=r"(r[2]), "=r"(r[3]) : "r"(addr));
}
__device__ __forceinline__ void mma_fp16(float d[4], const unsigned a[4],
                                         unsigned b0, unsigned b1) {
    asm volatile("mma.sync.aligned.m16n8k16.row.col.f32.f16.f16.f32 "
        "{%0,%1,%2,%3}, {%4,%5,%6,%7}, {%8,%9}, {%0,%1,%2,%3};"
        : "+f"(d[0]), "+f"(d[1]), "+f"(d[2]), "+f"(d[3])
        : "r"(a[0]), "r"(a[1]), "r"(a[2]), "r"(a[3]), "r"(b0), "r"(b1));
}
__device__ __forceinline__ float ex2f(float x) {
    float r;
    asm("ex2.approx.ftz.f32 %0, %1;" : "=f"(r) : "f"(x));
    return r;
}
__device__ __forceinline__ unsigned packh2(float lo, float hi) {
    __half2 h2 = __floats2half2_rn(lo, hi);
    return *(unsigned*)&h2;
}
__device__ __forceinline__ unsigned hadd2u(unsigned a, unsigned b) {
    __half2 r = __hadd2(*(__half2*)&a, *(__half2*)&b);
    return *(unsigned*)&r;
}
__device__ __forceinline__ unsigned hsub2u(unsigned a, unsigned b) {
    __half2 r = __hsub2(*(__half2*)&a, *(__half2*)&b);
    return *(unsigned*)&r;
}
__device__ __forceinline__ unsigned hmax2u(unsigned a, unsigned b) {
    __half2 r = __hmax2(*(__half2*)&a, *(__half2*)&b);
    return *(unsigned*)&r;
}
__device__ __forceinline__ unsigned hexp2u(unsigned x) {
    unsigned r;
    asm("ex2.approx.f16x2 %0, %1;" : "=r"(r) : "r"(x));
    return r;
}
#define CP16(saddr, gptr) \
    asm volatile("cp.async.cg.shared.global [%0], [%1], 16;" :: "r"(saddr), "l"(gptr))
#define CP_COMMIT() asm volatile("cp.async.commit_group;" ::: "memory")
#define CP_WAIT0() asm volatile("cp.async.wait_group 0;" ::: "memory")
#define CP_WAIT1() asm volatile("cp.async.wait_group 1;" ::: "memory")

#define SCLF 0.18033688f   // 0.125 * log2(e)

// ---------------- weight prep: transpose + fp16 hi/lo split ----------------
__global__ void wprep4(const float* __restrict__ W0, const float* __restrict__ W1,
                       const float* __restrict__ W2, const float* __restrict__ W3,
                       __half* __restrict__ Th, __half* __restrict__ Tl)
{
    __shared__ float tile[32][33];
    int z = blockIdx.z;
    const float* W = z == 0 ? W0 : z == 1 ? W1 : z == 2 ? W2 : W3;
    __half* th = Th + (size_t)z * H_ * H_;
    __half* tl = Tl + (size_t)z * H_ * H_;
    int k0 = blockIdx.x * 32, n0 = blockIdx.y * 32;
    int tx = threadIdx.x, ty = threadIdx.y;
    for (int i = ty; i < 32; i += 8)
        tile[i][tx] = W[(size_t)(k0 + i) * H_ + n0 + tx];
    __syncthreads();
    for (int i = ty; i < 32; i += 8) {
        float v = tile[tx][i];
        __half h = __float2half_rn(v);
        __half l = __float2half_rn(v - __half2float(h));
        size_t o = (size_t)(n0 + i) * H_ + k0 + tx;
        th[o] = h;
        tl[o] = l;
    }
}

// ---------------- elementwise fp16 convert (cross_states) ----------------
__global__ void conv16(const float* __restrict__ x, __half* __restrict__ o)
{
    int idx = (blockIdx.x * 256 + threadIdx.x) * 4;
    float4 v = *(const float4*)(x + idx);
    uint2 r;
    r.x = packh2(v.x, v.y);
    r.y = packh2(v.z, v.w);
    *(uint2*)(o + idx) = r;
}

// ---------------- mask int32 -> half additive bias (0 / -30000) ----------------
__global__ void maskprep(const int* __restrict__ m, __half* __restrict__ o)
{
    size_t i = ((size_t)blockIdx.x * 256 + threadIdx.x);
    const int4* mp = (const int4*)(m + i * 8);
    int4 a = mp[0], b = mp[1];
    uint4 r;
    r.x = packh2(a.x ? 0.f : -30000.f, a.y ? 0.f : -30000.f);
    r.y = packh2(a.z ? 0.f : -30000.f, a.w ? 0.f : -30000.f);
    r.z = packh2(b.x ? 0.f : -30000.f, b.y ? 0.f : -30000.f);
    r.w = packh2(b.z ? 0.f : -30000.f, b.w ? 0.f : -30000.f);
    *(uint4*)(o + i * 8) = r;
}

// ---------------- LayerNorm -> fp16 ----------------
__global__ void ln_kernel(const float* __restrict__ x, const float* __restrict__ gam,
                          const float* __restrict__ bet, __half* __restrict__ o)
{
    int row = blockIdx.x;
    int t = threadIdx.x;
    const float* xr = x + (size_t)row * H_;
    float v0 = xr[t], v1 = xr[t+256], v2 = xr[t+512];
    float s  = v0 + v1 + v2;
    float sq = v0*v0 + v1*v1 + v2*v2;
    #pragma unroll
    for (int off = 16; off; off >>= 1) {
        s  += __shfl_xor_sync(~0u, s,  off);
        sq += __shfl_xor_sync(~0u, sq, off);
    }
    __shared__ float rs[8], rq[8];
    int w = t >> 5;
    if ((t & 31) == 0) { rs[w] = s; rq[w] = sq; }
    __syncthreads();
    if (t < 32) {
        float a  = (t < 8) ? rs[t] : 0.f;
        float b2 = (t < 8) ? rq[t] : 0.f;
        #pragma unroll
        for (int off = 4; off; off >>= 1) {
            a  += __shfl_xor_sync(~0u, a,  off);
            b2 += __shfl_xor_sync(~0u, b2, off);
        }
        if (t == 0) { rs[0] = a; rq[0] = b2; }
    }
    __syncthreads();
    float mu  = rs[0] * (1.f / H_);
    float var = rq[0] * (1.f / H_) - mu * mu;
    float r   = rsqrtf(var + 1e-5f);
    __half* orow = o + (size_t)row * H_;
    #pragma unroll
    for (int e = 0; e < 3; e++) {
        int c = t + e * 256;
        float val = ((e==0?v0:e==1?v1:v2) - mu) * r * gam[c] + bet[c];
        orow[c] = __float2half_rn(val);
    }
}

// ---------------- GEMM: A fp16 x W fp16-hi/lo (2-term), cp.async 2-stage ----------------
#define GP2 40
#define GPLANE (128*GP2)
#define GSMEM (int)(2*3*GPLANE*sizeof(__half))   // 61440

__global__ void __launch_bounds__(256, 2) gemm_qkv(
    const __half* __restrict__ xn16, const __half* __restrict__ cr16,
    const __half* __restrict__ wth, const __half* __restrict__ wtl,
    const float* __restrict__ bq, const float* __restrict__ bk, const float* __restrict__ bv,
    const float* __restrict__ mem,
    const float* __restrict__ gate, const float* __restrict__ gbias,
    const float* __restrict__ dyn,
    __half* __restrict__ q16, __half* __restrict__ k16, __half* __restrict__ v16,
    float* __restrict__ Cf, int fused)
{
    extern __shared__ __half gsm[];
    int t = threadIdx.x, w = t >> 5, lane = t & 31;
    int wm = w & 1, wn = w >> 1;
    int m0 = blockIdx.x * 128, n0 = blockIdx.y * 128;
    int g = lane >> 2, qd = lane & 3;
    int z = blockIdx.z;

    const __half *A, *Bh, *Bl;
    const float *bias, *memadd = nullptr;
    __half *Co = nullptr;
    int mode;   // 0 Q (scale), 1 +mem, 2 gate/dyn->float
    if (fused) {
        A = xn16; Bh = wth; Bl = wtl; bias = bq; mode = 2;
    } else if (z == 0) {
        A = xn16; Bh = wth; Bl = wtl; bias = bq; mode = 0; Co = q16;
    } else if (z == 1) {
        A = cr16; Bh = wth + (size_t)H_*H_; Bl = wtl + (size_t)H_*H_;
        bias = bk; mode = 1; memadd = mem; Co = k16;
    } else {
        A = cr16; Bh = wth + 2*(size_t)H_*H_; Bl = wtl + 2*(size_t)H_*H_;
        bias = bv; mode = 1; memadd = mem + (size_t)ROWS*H_; Co = v16;
    }

    auto load_stage = [&](int k0, int s) {
        #pragma unroll
        for (int p = 0; p < 3; p++) {
            const __half* src = p == 0 ? A : p == 1 ? Bh : Bl;
            int rbase = (p == 0) ? m0 : n0;
            __half* dst = gsm + (s*3 + p) * GPLANE;
            #pragma unroll
            for (int i = t; i < 512; i += 256) {
                int r = i >> 2, c = (i & 3) * 8;
                CP16(sa(dst + r*GP2 + c), src + (size_t)(rbase + r) * H_ + k0 + c);
            }
        }
        CP_COMMIT();
    };

    float acc[4][4][4] = {};
    int lr = lane & 15, lc = (lane >> 4) * 8;

    const unsigned aB0 = sa(gsm + 0*GPLANE + (wm*64 + lr)*GP2 + lc);
    const unsigned bH0 = sa(gsm + 1*GPLANE + (wn*32 + lr)*GP2 + lc);
    const unsigned bL0 = sa(gsm + 2*GPLANE + (wn*32 + lr)*GP2 + lc);
    const unsigned SOFF = 3*GPLANE*2;

    load_stage(0, 0);
    const int NIT = H_ / 32;
    for (int j = 0; j < NIT; j++) {
        int s = j & 1;
        if (j + 1 < NIT) { load_stage((j + 1) * 32, s ^ 1); CP_WAIT1(); }
        else             { CP_WAIT0(); }
        __syncthreads();

        unsigned so = s ? SOFF : 0;
        unsigned aB = aB0 + so, bH = bH0 + so, bL = bL0 + so;

        #pragma unroll
        for (int kh = 0; kh < 2; kh++) {
            unsigned a4[4][4], bh[2][4], bl[2][4];
            #pragma unroll
            for (int mt = 0; mt < 4; mt++)
                ldsm4(a4[mt], aB + (mt*16*GP2 + kh*16) * 2);
            #pragma unroll
            for (int ng = 0; ng < 2; ng++) {
                unsigned off = (ng*16*GP2 + kh*16) * 2;
                ldsm4(bh[ng], bH + off);
                ldsm4(bl[ng], bL + off);
            }
            #pragma unroll
            for (int mt = 0; mt < 4; mt++)
                #pragma unroll
                for (int ng = 0; ng < 2; ng++)
                    #pragma unroll
                    for (int tl = 0; tl < 2; tl++) {
                        float* d = acc[mt][ng*2 + tl];
                        mma_fp16(d, a4[mt], bh[ng][tl], bh[ng][tl+2]);
                        mma_fp16(d, a4[mt], bl[ng][tl], bl[ng][tl+2]);
                    }
        }
        __syncthreads();
    }

    float gv = 1.f, gb = 0.f;
    if (mode == 2) { gv = gate[0]; gb = gbias[0]; }
    #pragma unroll
    for (int mt = 0; mt < 4; mt++) {
        #pragma unroll
        for (int nt = 0; nt < 4; nt++) {
            int col = n0 + wn*32 + nt*8 + qd*2;
            float2 bvv = *(const float2*)(bias + col);
            #pragma unroll
            for (int rj = 0; rj < 2; rj++) {
                int row = m0 + wm*64 + mt*16 + g + rj*8;
                float x0 = acc[mt][nt][rj*2]   + bvv.x;
                float x1 = acc[mt][nt][rj*2+1] + bvv.y;
                if (mode == 1) {
                    float2 mm = *(const float2*)(memadd + (size_t)row * H_ + col);
                    x0 += 0.5f * mm.x; x1 += 0.5f * mm.y;
                }
                size_t o = (size_t)row * H_ + col;
                if (mode == 2) {
                    float d = dyn[row];
                    x0 = (x0*gv + gb) * d; x1 = (x1*gv + gb) * d;
                    *(float2*)(Cf + o) = make_float2(x0, x1);
                } else {
                    if (mode == 0) { x0 *= SCLF; x1 *= SCLF; }   // fold softmax scale into Q
                    *(unsigned*)(Co + o) = packh2(x0, x1);
                }
            }
        }
    }
}

// ---------------- Flash attention: fp16 mma, fp16x2 softmax, tensor-core denominator ----------------
#define FP  72     // Q/K plane pad (halves)
#define VP  88     // V plane pad: cols 64..71 = ones (denominator), 72..79 = 0
#define MP2 72     // mask plane pad (halves)
#define NKT (S_/64)
// smem: Q 64*FP | K 2x64*FP | V 2x64*VP | maskbias 2x64*MP2   (halves)
#define FSMEM (int)((64*FP + 2*64*FP + 2*64*VP + 2*64*MP2) * 2)   // 68608

__global__ void __launch_bounds__(128) flash_mma(
    const __half* __restrict__ q16, const __half* __restrict__ k16,
    const __half* __restrict__ v16,
    const __half* __restrict__ maskb,
    __half* __restrict__ ao16)
{
    extern __shared__ char fsm[];
    __half* Qs = (__half*)fsm;
    __half* Ks = Qs + 64*FP;
    __half* Vp = Ks + 2*64*FP;
    __half* Mb = Vp + 2*64*VP;

    int t = threadIdx.x, w = t >> 5, lane = t & 31;
    int g = lane >> 2, qd = lane & 3;
    int q0 = blockIdx.x * 64, h = blockIdx.y, b = blockIdx.z;
    const size_t basec = (size_t)b * S_ * H_ + h * 64;
    const __half* mbh = maskb + (size_t)b * S_ * S_;

    // Q load (pre-scaled by SCLF at projection)
    for (int i = t; i < 512; i += 128) {
        int r = i >> 3, c = (i & 7) * 8;
        *(uint4*)&Qs[r*FP + c] = *(const uint4*)(q16 + basec + (size_t)(q0 + r) * H_ + c);
    }
    // V pad init (both stages): cols 64..71 = 1 (denominator columns — every qd
    // lane's D-fragment column must hit a ones column), 72..79 = 0
    {
        int s = t >> 6, r = t & 63;
        __half* vp = Vp + s*64*VP + r*VP;
        #pragma unroll
        for (int c = 64; c < 72; c++) vp[c] = __float2half(1.f);
        #pragma unroll
        for (int c = 72; c < 80; c++) vp[c] = __float2half(0.f);
    }

    auto load_stage = [&](int k0, int s) {
        __half* kd = Ks + s*64*FP;
        __half* vd = Vp + s*64*VP;
        __half* md = Mb + s*64*MP2;
        #pragma unroll
        for (int i = t; i < 512; i += 128) {
            int r = i >> 3, c = (i & 7) * 8;
            CP16(sa(kd + r*FP + c), k16 + basec + (size_t)(k0 + r) * H_ + c);
            CP16(sa(vd + r*VP + c), v16 + basec + (size_t)(k0 + r) * H_ + c);
            CP16(sa(md + r*MP2 + c), mbh + (size_t)(q0 + r) * S_ + k0 + c);
        }
        CP_COMMIT();
    };

    load_stage(0, 0);
    __syncthreads();

    int lr = lane & 15, lc = (lane >> 4) * 8;
    unsigned qf[4][4];
    #pragma unroll
    for (int kb = 0; kb < 4; kb++)
        ldsm4(qf[kb], sa(&Qs[(w*16 + lr)*FP + lc + kb*16]));

    float mrow[2] = {-CUDART_INF_F, -CUDART_INF_F};
    float oacc[8][4] = {};
    float dacc[4] = {};

    for (int j = 0; j < NKT; j++) {
        int s = j & 1;
        if (j + 1 < NKT) { load_stage((j + 1) * 64, s ^ 1); CP_WAIT1(); }
        else             { CP_WAIT0(); }
        __syncthreads();

        const __half* Kss = Ks + s*64*FP;
        const __half* Vss = Vp + s*64*VP;
        const __half* msp = Mb + s*64*MP2;

        // S = Q K^T (Q pre-scaled)
        float sreg[8][4] = {};
        #pragma unroll
        for (int kb = 0; kb < 4; kb++) {
            #pragma unroll
            for (int ng = 0; ng < 4; ng++) {
                unsigned b4[4];
                ldsm4(b4, sa(Kss) + ((ng*16 + lr)*FP + lc + kb*16) * 2);
                #pragma unroll
                for (int tl = 0; tl < 2; tl++)
                    mma_fp16(sreg[ng*2 + tl], qf[kb], b4[tl], b4[tl+2]);
            }
        }

        // convert to fp16x2 fragments + additive mask bias
        unsigned pf[4][4];
        const int rbase = (w*16 + g)*MP2 + qd*2;
        #pragma unroll
        for (int kb = 0; kb < 4; kb++) {
            pf[kb][0] = packh2(sreg[2*kb][0],   sreg[2*kb][1]);
            pf[kb][1] = packh2(sreg[2*kb][2],   sreg[2*kb][3]);
            pf[kb][2] = packh2(sreg[2*kb+1][0], sreg[2*kb+1][1]);
            pf[kb][3] = packh2(sreg[2*kb+1][2], sreg[2*kb+1][3]);
            #pragma unroll
            for (int jj = 0; jj < 4; jj++) {
                int nt = kb*2 + (jj >> 1);
                unsigned mv = *(const unsigned*)&msp[rbase + (jj & 1)*8*MP2 + nt*8];
                pf[kb][jj] = hadd2u(pf[kb][jj], mv);
            }
        }

        // row max (fp16x2 tree, finalize fp32)
        unsigned mx2[2] = { pf[0][0], pf[0][1] };
        mx2[0] = hmax2u(mx2[0], pf[0][2]);
        mx2[1] = hmax2u(mx2[1], pf[0][3]);
        #pragma unroll
        for (int kb = 1; kb < 4; kb++) {
            mx2[0] = hmax2u(hmax2u(mx2[0], pf[kb][0]), pf[kb][2]);
            mx2[1] = hmax2u(hmax2u(mx2[1], pf[kb][1]), pf[kb][3]);
        }
        float corr[2];
        unsigned nmu[2];
        bool upd = false;
        #pragma unroll
        for (int rj = 0; rj < 2; rj++) {
            __half2 m2 = *(__half2*)&mx2[rj];
            float mx = fmaxf(__low2float(m2), __high2float(m2));
            mx = fmaxf(mx, __shfl_xor_sync(~0u, mx, 1));
            mx = fmaxf(mx, __shfl_xor_sync(~0u, mx, 2));
            float nm = fmaxf(mrow[rj], mx);
            __half nmh = __float2half_rn(nm);
            float nmr = __half2float(nmh);
            upd = upd || (nmr != mrow[rj]);
            corr[rj] = ex2f(mrow[rj] - nmr);    // 1.0 when unchanged; 0 on first tile
            mrow[rj] = nmr;
            __half2 nm2 = __half2half2(nmh);
            nmu[rj] = *(unsigned*)&nm2;
        }

        // P = exp2(S - nm), fp16x2
        #pragma unroll
        for (int kb = 0; kb < 4; kb++)
            #pragma unroll
            for (int jj = 0; jj < 4; jj++)
                pf[kb][jj] = hexp2u(hsub2u(pf[kb][jj], nmu[jj & 1]));

        // rescale accumulators (skip when no row in warp updated its max)
        if (__any_sync(~0u, upd)) {
            #pragma unroll
            for (int nt = 0; nt < 8; nt++) {
                oacc[nt][0] *= corr[0]; oacc[nt][1] *= corr[0];
                oacc[nt][2] *= corr[1]; oacc[nt][3] *= corr[1];
            }
            dacc[0] *= corr[0]; dacc[1] *= corr[0];
            dacc[2] *= corr[1]; dacc[3] *= corr[1];
        }

        // O += P V ; D += P 1 (ones columns 64..71 of padded V)
        #pragma unroll
        for (int kb = 0; kb < 4; kb++) {
            #pragma unroll
            for (int ng = 0; ng < 4; ng++) {
                unsigned v4[4];
                ldsm4t(v4, sa(Vss) + ((kb*16 + lr)*VP + ng*16 + lc) * 2);
                #pragma unroll
                for (int tl = 0; tl < 2; tl++)
                    mma_fp16(oacc[ng*2 + tl], pf[kb], v4[tl*2], v4[tl*2+1]);
            }
            unsigned v4[4];
            ldsm4t(v4, sa(Vss) + ((kb*16 + lr)*VP + 64 + lc) * 2);
            mma_fp16(dacc, pf[kb], v4[0], v4[1]);
        }
        __syncthreads();
    }

    // epilogue: normalize by tensor-core denominator (valid in every lane now)
    float inv0 = dacc[0] > 0.f ? 1.f / dacc[0] : 0.f;
    float inv1 = dacc[2] > 0.f ? 1.f / dacc[2] : 0.f;
    #pragma unroll
    for (int rj = 0; rj < 2; rj++) {
        float inv = rj ? inv1 : inv0;
        int row = q0 + w*16 + g + rj*8;
        #pragma unroll
        for (int nt = 0; nt < 8; nt++) {
            int col = nt*8 + qd*2;
            size_t o = basec + (size_t)row * H_ + col;
            *(unsigned*)(ao16 + o) = packh2(oacc[nt][rj*2] * inv, oacc[nt][rj*2+1] * inv);
        }
    }
}

// ---------------- launch ----------------
extern "C" void kernel_launch(void* const* d_in, const int* in_sizes, int n_in,
                              void* d_out, int out_size)
{
    const float* hidden = (const float*)d_in[0];
    const float* cross  = (const float*)d_in[1];
    const int*   amask  = (const int*)  d_in[2];
    const float* mem    = (const float*)d_in[3];
    const float* dyn    = (const float*)d_in[4];
    const float* Wq = (const float*)d_in[5];  const float* bq = (const float*)d_in[6];
    const float* Wk = (const float*)d_in[7];  const float* bk = (const float*)d_in[8];
    const float* Wv = (const float*)d_in[9];  const float* bv = (const float*)d_in[10];
    const float* Wo = (const float*)d_in[11]; const float* bo = (const float*)d_in[12];
    const float* gate  = (const float*)d_in[13];
    const float* gbias = (const float*)d_in[14];
    const float* lng   = (const float*)d_in[15];
    const float* lnb   = (const float*)d_in[16];
    float* out = (float*)d_out;

    __half *xn16,*cr16,*q16,*k16,*v16,*ao16,*wth,*wtl,*mb;
    cudaGetSymbolAddress((void**)&xn16, g_xn16);
    cudaGetSymbolAddress((void**)&cr16, g_cr16);
    cudaGetSymbolAddress((void**)&q16,  g_q16);
    cudaGetSymbolAddress((void**)&k16,  g_k16);
    cudaGetSymbolAddress((void**)&v16,  g_v16);
    cudaGetSymbolAddress((void**)&ao16, g_ao16);
    cudaGetSymbolAddress((void**)&wth,  g_wt_hi);
    cudaGetSymbolAddress((void**)&wtl,  g_wt_lo);
    cudaGetSymbolAddress((void**)&mb,   g_maskb);

    cudaFuncSetAttribute(gemm_qkv, cudaFuncAttributeMaxDynamicSharedMemorySize, GSMEM);
    cudaFuncSetAttribute(flash_mma, cudaFuncAttributeMaxDynamicSharedMemorySize, FSMEM);

    wprep4<<<dim3(H_/32, H_/32, 4), dim3(32,8)>>>(Wq, Wk, Wv, Wo, wth, wtl);
    ln_kernel<<<ROWS, 256>>>(hidden, lng, lnb, xn16);
    conv16<<<ROWS*H_/1024, 256>>>(cross, cr16);
    maskprep<<<(size_t)B_*S_*S_/8/256, 256>>>(amask, mb);

    gemm_qkv<<<dim3(ROWS/128, H_/128, 3), 256, GSMEM>>>(
        xn16, cr16, wth, wtl, bq, bk, bv, mem,
        nullptr, nullptr, nullptr,
        q16, k16, v16, nullptr, 0);

    flash_mma<<<dim3(S_/64, NH_, B_), 128, FSMEM>>>(q16, k16, v16, mb, ao16);

    gemm_qkv<<<dim3(ROWS/128, H_/128, 1), 256, GSMEM>>>(
        ao16, nullptr, wth + 3*(size_t)H_*H_, wtl + 3*(size_t)H_*H_,
        bo, nullptr, nullptr, nullptr,
        gate, gbias, dyn,
        nullptr, nullptr, nullptr, out, 1);
}